// round 5
// baseline (speedup 1.0000x reference)
#include <cuda_runtime.h>
#include <cuda_fp16.h>
#include <cstdint>

#define D        128
#define MAXN     100000
#define MAXE     1600000
#define TM       64
#define GTHREADS 256
#define WS_STRIDE 132
#define SCAN_T   256

// -------- device scratch --------
__device__ __half g_h[MAXN * D];      // post-GEMM h (normalized*1.8), fp16
__device__ float  g_agg[MAXN * D];    // layer-1 aggregate (fp32, feeds GEMM2)
__device__ int    g_degO[MAXN];
__device__ int    g_degI[MAXN];
__device__ float  g_nO[MAXN];
__device__ float  g_nI[MAXN];
__device__ int    g_rowptr[MAXN + 1];
__device__ int    g_esrc[MAXE];       // CSR column indices
__device__ float  g_esc[MAXE];        // per-edge scale nO[src]
__device__ int    g_bsum[512];
__device__ int    g_fill[MAXN + 1];   // CSR fill cursor (pre-seeded with rowptr)

// -------- f32x2 packed-FMA helpers --------
__device__ __forceinline__ unsigned long long fma2(unsigned long long a,
                                                   unsigned long long b,
                                                   unsigned long long c) {
    unsigned long long d;
    asm("fma.rn.f32x2 %0, %1, %2, %3;" : "=l"(d) : "l"(a), "l"(b), "l"(c));
    return d;
}
__device__ __forceinline__ unsigned long long splat2(float x) {
    unsigned long long d;
    asm("mov.b64 %0, {%1, %1};" : "=l"(d) : "f"(x));
    return d;
}
__device__ __forceinline__ void unpack2(unsigned long long v, float& lo, float& hi) {
    asm("mov.b64 {%0, %1}, %2;" : "=f"(lo), "=f"(hi) : "l"(v));
}

// -------- degree --------
__global__ void zero_deg_k(int n) {
    int i = blockIdx.x * blockDim.x + threadIdx.x;
    if (i < n) { g_degO[i] = 0; g_degI[i] = 0; }
}
__global__ void degree_k(const int* __restrict__ src, const int* __restrict__ dst, int E) {
    int e = blockIdx.x * blockDim.x + threadIdx.x;
    if (e < E) { atomicAdd(&g_degO[src[e]], 1); atomicAdd(&g_degI[dst[e]], 1); }
}

// -------- prefix scan over degI -> rowptr; fused norms + cursor seed --------
__global__ void scan_block_k(int n) {
    __shared__ int s[SCAN_T];
    int i = blockIdx.x * SCAN_T + threadIdx.x;
    int v = (i < n) ? g_degI[i] : 0;
    s[threadIdx.x] = v;
    __syncthreads();
    #pragma unroll
    for (int off = 1; off < SCAN_T; off <<= 1) {
        int t = (threadIdx.x >= off) ? s[threadIdx.x - off] : 0;
        __syncthreads();
        s[threadIdx.x] += t;
        __syncthreads();
    }
    if (i < n) g_rowptr[i + 1] = s[threadIdx.x];
    if (threadIdx.x == SCAN_T - 1) g_bsum[blockIdx.x] = s[SCAN_T - 1];
}
__global__ void scan_bsum_k(int nb) {
    __shared__ int s[512];
    int v = (threadIdx.x < nb) ? g_bsum[threadIdx.x] : 0;
    s[threadIdx.x] = v;
    __syncthreads();
    #pragma unroll
    for (int off = 1; off < 512; off <<= 1) {
        int t = (threadIdx.x >= off) ? s[threadIdx.x - off] : 0;
        __syncthreads();
        s[threadIdx.x] += t;
        __syncthreads();
    }
    if (threadIdx.x < nb) g_bsum[threadIdx.x] = s[threadIdx.x] - v;
}
__global__ void scan_add_norm_k(int n) {
    int i = blockIdx.x * SCAN_T + threadIdx.x;
    if (i < n) {
        int v = g_rowptr[i + 1] + g_bsum[blockIdx.x];
        g_rowptr[i + 1] = v;
        g_fill[i + 1]   = v;
        g_nO[i] = rsqrtf(fmaxf((float)g_degO[i], 1.0f));
        g_nI[i] = rsqrtf(fmaxf((float)g_degI[i], 1.0f));
    }
    if (i == 0) { g_rowptr[0] = 0; g_fill[0] = 0; }
}
__global__ void fill_k(const int* __restrict__ src, const int* __restrict__ dst, int E) {
    int e = blockIdx.x * blockDim.x + threadIdx.x;
    if (e < E) {
        int s = src[e];
        int pos = atomicAdd(&g_fill[dst[e]], 1);
        g_esrc[pos] = s;
        g_esc[pos]  = g_nO[s];
    }
}

// -------- fused GEMM + bias + L2-normalize*1.8 (graph-independent) --------
__global__ void __launch_bounds__(GTHREADS, 2)
gemm_norm_k(const float* __restrict__ X,
            const float* __restrict__ W,
            const float* __restrict__ b,
            __half* __restrict__ Hout,
            int N)
{
    extern __shared__ float sm[];
    float* ws = sm;                    // ws[k*WS_STRIDE + c] = W[c][k]
    float* xs = sm + D * WS_STRIDE;    // [TM][D]
    const int tid = threadIdx.x;
    const int nb  = blockIdx.x * TM;

    for (int i = tid; i < D * D; i += GTHREADS) {
        int c = i >> 7, k = i & (D - 1);
        ws[k * WS_STRIDE + c] = W[i];
    }
    for (int i = tid; i < TM * D; i += GTHREADS) {
        int node = nb + (i >> 7);
        xs[i] = (node < N) ? X[(size_t)node * D + (i & (D - 1))] : 0.f;
    }
    __syncthreads();

    const int cg = tid & 31;
    const int c0 = cg * 4;
    const int n0 = (tid >> 5) * 8;

    unsigned long long acc2[8][2];
    #pragma unroll
    for (int i = 0; i < 8; i++) { acc2[i][0] = 0ull; acc2[i][1] = 0ull; }

    #pragma unroll 4
    for (int k4 = 0; k4 < D / 4; k4++) {
        ulonglong2 wq0 = *(const ulonglong2*)&ws[(4 * k4 + 0) * WS_STRIDE + c0];
        ulonglong2 wq1 = *(const ulonglong2*)&ws[(4 * k4 + 1) * WS_STRIDE + c0];
        ulonglong2 wq2 = *(const ulonglong2*)&ws[(4 * k4 + 2) * WS_STRIDE + c0];
        ulonglong2 wq3 = *(const ulonglong2*)&ws[(4 * k4 + 3) * WS_STRIDE + c0];
        #pragma unroll
        for (int i = 0; i < 8; i++) {
            const float4 xv = *(const float4*)&xs[(n0 + i) * D + 4 * k4];
            unsigned long long x0 = splat2(xv.x);
            unsigned long long x1 = splat2(xv.y);
            unsigned long long x2 = splat2(xv.z);
            unsigned long long x3 = splat2(xv.w);
            acc2[i][0] = fma2(x0, wq0.x, acc2[i][0]);
            acc2[i][1] = fma2(x0, wq0.y, acc2[i][1]);
            acc2[i][0] = fma2(x1, wq1.x, acc2[i][0]);
            acc2[i][1] = fma2(x1, wq1.y, acc2[i][1]);
            acc2[i][0] = fma2(x2, wq2.x, acc2[i][0]);
            acc2[i][1] = fma2(x2, wq2.y, acc2[i][1]);
            acc2[i][0] = fma2(x3, wq3.x, acc2[i][0]);
            acc2[i][1] = fma2(x3, wq3.y, acc2[i][1]);
        }
    }

    const float4 bb = *(const float4*)&b[c0];
    #pragma unroll
    for (int i = 0; i < 8; i++) {
        float a0, a1, a2, a3;
        unpack2(acc2[i][0], a0, a1);
        unpack2(acc2[i][1], a2, a3);
        a0 += bb.x; a1 += bb.y; a2 += bb.z; a3 += bb.w;
        float s = a0 * a0 + a1 * a1 + a2 * a2 + a3 * a3;
        #pragma unroll
        for (int off = 16; off; off >>= 1) s += __shfl_xor_sync(0xffffffffu, s, off);
        const int node = nb + n0 + i;
        if (node < N) {
            const float sc = 1.8f / fmaxf(sqrtf(s), 1e-12f);
            __half2 h0 = __float22half2_rn(make_float2(a0 * sc, a1 * sc));
            __half2 h1 = __float22half2_rn(make_float2(a2 * sc, a3 * sc));
            uint2 o;
            o.x = *(uint32_t*)&h0;
            o.y = *(uint32_t*)&h1;
            *(uint2*)&Hout[(size_t)node * D + c0] = o;
        }
    }
}

// -------- CSR gather with fused norms: out[d,:] = nI[d] * sum nO[s]*h[s,:] --------
__device__ __forceinline__ void acc_row(float4& acc, const __half* __restrict__ h,
                                        int s, float sc, int j4) {
    uint2 u = *(const uint2*)&h[(size_t)s * D + j4];
    __half2 p0 = *(__half2*)&u.x;
    __half2 p1 = *(__half2*)&u.y;
    float2 f0 = __half22float2(p0);
    float2 f1 = __half22float2(p1);
    acc.x = fmaf(sc, f0.x, acc.x);
    acc.y = fmaf(sc, f0.y, acc.y);
    acc.z = fmaf(sc, f1.x, acc.z);
    acc.w = fmaf(sc, f1.y, acc.w);
}

__global__ void gather_k(const __half* __restrict__ h,
                         float* __restrict__ out,
                         int N)
{
    const int node = blockIdx.x * 8 + (threadIdx.x >> 5);
    if (node >= N) return;
    const int lane = threadIdx.x & 31;
    const int j4 = lane * 4;
    const int start = g_rowptr[node];
    const int end   = g_rowptr[node + 1];

    float4 acc = make_float4(0.f, 0.f, 0.f, 0.f);

    for (int base = start; base < end; base += 32) {
        const int e = base + lane;
        const int   s  = (e < end) ? g_esrc[e] : 0;
        const float sc = (e < end) ? g_esc[e]  : 0.f;
        const int cnt = min(32, end - base);
        int j = 0;
        for (; j + 8 <= cnt; j += 8) {
            #pragma unroll
            for (int q = 0; q < 8; q++) {
                int   sq = __shfl_sync(0xffffffffu, s,  j + q);
                float cq = __shfl_sync(0xffffffffu, sc, j + q);
                acc_row(acc, h, sq, cq, j4);
            }
        }
        for (; j < cnt; j++) {
            int   sq = __shfl_sync(0xffffffffu, s,  j);
            float cq = __shfl_sync(0xffffffffu, sc, j);
            acc_row(acc, h, sq, cq, j4);
        }
    }

    const float sc = g_nI[node];
    acc.x *= sc; acc.y *= sc; acc.z *= sc; acc.w *= sc;
    *(float4*)&out[(size_t)node * D + j4] = acc;
}

extern "C" void kernel_launch(void* const* d_in, const int* in_sizes, int n_in,
                              void* d_out, int out_size)
{
    const float* x   = (const float*)d_in[0];
    const float* W1  = (const float*)d_in[1];
    const float* b1  = (const float*)d_in[2];
    const float* W2  = (const float*)d_in[3];
    const float* b2  = (const float*)d_in[4];
    const int*   src = (const int*)d_in[5];
    const int*   dst = (const int*)d_in[6];
    float* out = (float*)d_out;

    const int N = in_sizes[0] / D;
    const int E = in_sizes[5];

    __half* h_ptr;
    float*  agg_ptr;
    cudaGetSymbolAddress((void**)&h_ptr,   g_h);
    cudaGetSymbolAddress((void**)&agg_ptr, g_agg);

    const int SMEM_BYTES = (D * WS_STRIDE + TM * D) * (int)sizeof(float);
    cudaFuncSetAttribute(gemm_norm_k, cudaFuncAttributeMaxDynamicSharedMemorySize, SMEM_BYTES);

    const int nBlkGemm   = (N + TM - 1) / TM;
    const int nBlkNode   = (N + 255) / 256;
    const int nBlkEdge   = (E + 255) / 256;
    const int nBlkScan   = (N + SCAN_T - 1) / SCAN_T;
    const int nBlkGather = (N + 7) / 8;

    // one-time side stream + events for fork-join capture (resources only; work
    // per call is identical regardless)
    static cudaStream_t s_side = nullptr;
    static cudaEvent_t  ev_fork = nullptr, ev_join = nullptr;
    static int stream_ok = -1;
    if (stream_ok < 0) {
        stream_ok = (cudaStreamCreateWithFlags(&s_side, cudaStreamNonBlocking) == cudaSuccess &&
                     cudaEventCreateWithFlags(&ev_fork, cudaEventDisableTiming) == cudaSuccess &&
                     cudaEventCreateWithFlags(&ev_join, cudaEventDisableTiming) == cudaSuccess)
                    ? 1 : 0;
    }

    if (stream_ok) {
        // fork: CSR/degree prepass on side stream, concurrent with layer-1 GEMM
        cudaEventRecord(ev_fork, 0);
        cudaStreamWaitEvent(s_side, ev_fork, 0);

        zero_deg_k<<<nBlkNode, 256, 0, s_side>>>(N);
        degree_k<<<nBlkEdge, 256, 0, s_side>>>(src, dst, E);
        scan_block_k<<<nBlkScan, SCAN_T, 0, s_side>>>(N);
        scan_bsum_k<<<1, 512, 0, s_side>>>(nBlkScan);
        scan_add_norm_k<<<nBlkScan, SCAN_T, 0, s_side>>>(N);
        fill_k<<<nBlkEdge, 256, 0, s_side>>>(src, dst, E);
        cudaEventRecord(ev_join, s_side);

        gemm_norm_k<<<nBlkGemm, GTHREADS, SMEM_BYTES>>>(x, W1, b1, h_ptr, N);

        // join before gather needs CSR
        cudaStreamWaitEvent(0, ev_join, 0);
    } else {
        zero_deg_k<<<nBlkNode, 256>>>(N);
        degree_k<<<nBlkEdge, 256>>>(src, dst, E);
        scan_block_k<<<nBlkScan, SCAN_T>>>(N);
        scan_bsum_k<<<1, 512>>>(nBlkScan);
        scan_add_norm_k<<<nBlkScan, SCAN_T>>>(N);
        fill_k<<<nBlkEdge, 256>>>(src, dst, E);
        gemm_norm_k<<<nBlkGemm, GTHREADS, SMEM_BYTES>>>(x, W1, b1, h_ptr, N);
    }

    gather_k<<<nBlkGather, 256>>>(h_ptr, agg_ptr, N);
    gemm_norm_k<<<nBlkGemm, GTHREADS, SMEM_BYTES>>>(agg_ptr, W2, b2, h_ptr, N);
    gather_k<<<nBlkGather, 256>>>(h_ptr, out, N);
}